// round 7
// baseline (speedup 1.0000x reference)
#include <cuda_runtime.h>
#include <math.h>

#define NN 100000
#define NE 3200000
#define HID 16
#define NBLK 391                 // ceil(NN/256)
#define NP (NBLK * 256)          // 100096 padded

// Scratch (static device globals — zero-initialized at load)
__device__ int   d_cnt[NP];      // per-SRC out-degree counts; re-zeroed in scan3
__device__ int   d_bsum[NBLK];
__device__ int   d_bpre[NBLK];
__device__ int   d_off[NN + 1];  // CSC offsets (by src)
__device__ int   d_cur[NN];      // fill cursors; re-zeroed in k_dinv
__device__ float d_deg[NN];      // weighted in-degree; re-zeroed in k_dinv
__device__ int2  d_adj[NE];      // (dst, weight-bits) sorted by src
__device__ float d_dinv[NN];
__device__ float d_g  [NN * HID];
__device__ float d_agg[NN * HID];

// ---- 1. count out-edges per source + weighted in-degree per dest ---------
__global__ void k_count_deg(const int* __restrict__ row,
                            const int* __restrict__ col,
                            const float* __restrict__ ew) {
    int e = blockIdx.x * blockDim.x + threadIdx.x;
    if (e < NE) {
        atomicAdd(&d_cnt[row[e]], 1);
        atomicAdd(&d_deg[col[e]], ew[e]);
    }
}

// ---- 2a. per-block sums ----------------------------------------------------
__global__ void k_scan1() {
    __shared__ int s[256];
    int t = threadIdx.x;
    s[t] = d_cnt[blockIdx.x * 256 + t];
    __syncthreads();
    for (int d = 128; d > 0; d >>= 1) {
        if (t < d) s[t] += s[t + d];
        __syncthreads();
    }
    if (t == 0) d_bsum[blockIdx.x] = s[0];
}

// ---- 2b. scan of block sums (single block) ---------------------------------
__global__ void k_scan2() {
    __shared__ int s[512];
    int t = threadIdx.x;
    int v = (t < NBLK) ? d_bsum[t] : 0;
    s[t] = v;
    __syncthreads();
    for (int d = 1; d < 512; d <<= 1) {
        int a = (t >= d) ? s[t - d] : 0;
        __syncthreads();
        s[t] += a;
        __syncthreads();
    }
    if (t < NBLK) d_bpre[t] = s[t] - v;   // exclusive
}

// ---- 2c. final offsets; reset counts for next replay -----------------------
__global__ void k_scan3() {
    __shared__ int s[256];
    int t  = threadIdx.x;
    int gi = blockIdx.x * 256 + t;
    int v  = d_cnt[gi];
    s[t] = v;
    __syncthreads();
    for (int d = 1; d < 256; d <<= 1) {
        int a = (t >= d) ? s[t - d] : 0;
        __syncthreads();
        s[t] += a;
        __syncthreads();
    }
    if (gi <= NN) d_off[gi] = d_bpre[blockIdx.x] + s[t] - v;  // exclusive
    d_cnt[gi] = 0;
}

// ---- 3. fill CSC: scatter (dst, w) into src-sorted slots --------------------
__global__ void k_fill(const int* __restrict__ row,
                       const int* __restrict__ col,
                       const float* __restrict__ ew) {
    int e = blockIdx.x * blockDim.x + threadIdx.x;
    if (e >= NE) return;
    int src = row[e];
    int p = d_off[src] + atomicAdd(&d_cur[src], 1);
    d_adj[p] = make_int2(col[e], __float_as_int(ew[e]));
}

// ---- 4. dinv = rsqrt(1 + deg); reset deg + cursors --------------------------
__global__ void k_dinv() {
    int i = blockIdx.x * blockDim.x + threadIdx.x;
    if (i < NN) {
        float v = 1.0f + d_deg[i];
        d_dinv[i] = rsqrtf(v);
        d_deg[i] = 0.0f;
        d_cur[i] = 0;
    }
}

// ---- 5. layer-1 GEMM: g = dinv * (x @ W1); zero agg -------------------------
#define WPAD 144
__global__ void k_gemm1(const float* __restrict__ x,
                        const float* __restrict__ W1) {
    __shared__ float xs[16 * 128];
    __shared__ float Wt[HID * WPAD];
    int t = threadIdx.x;
    int base = blockIdx.x * 16;
    int nvalid = NN - base; if (nvalid > 16) nvalid = 16;

    const float4* xg = (const float4*)x + (size_t)base * 32;
    float4* xs4 = (float4*)xs;
    int n4 = nvalid * 32;
    for (int j = t; j < n4; j += 256) xs4[j] = xg[j];
    for (int j = t; j < 128 * HID; j += 256) {
        int k = j >> 4, c = j & 15;
        Wt[c * WPAD + k] = W1[j];
    }
    __syncthreads();

    int nloc = t >> 4;
    int node = base + nloc;
    int c    = t & 15;
    if (node >= NN) return;

    float acc = 0.0f;
    const float4* xrow = (const float4*)(xs + nloc * 128);
    const float*  wrow = Wt + c * WPAD;
#pragma unroll
    for (int kk = 0; kk < 32; kk++) {
        float4 xv = xrow[kk];
        float4 wv = *(const float4*)(wrow + kk * 4);
        acc += xv.x * wv.x + xv.y * wv.y + xv.z * wv.z + xv.w * wv.w;
    }
    int idx = node * HID + c;
    d_g[idx]   = d_dinv[node] * acc;
    d_agg[idx] = 0.0f;                      // zero for push pass 1
}

// ---- 6. PUSH aggregation (warp per source, fire-and-forget REDs) -----------
// g[src] loaded ONCE per node into registers; out-edges streamed coalesced;
// per edge: 4 lanes issue one red.global.add.v4.f32 each (no return latency).
__global__ void k_push() {
    int gw   = (blockIdx.x * blockDim.x + threadIdx.x) >> 5;
    int lane = threadIdx.x & 31;
    if (gw >= NN) return;
    int beg = d_off[gw], end = d_off[gw + 1];
    if (beg == end) return;
    int es = lane >> 2, q = lane & 3;

    float4 g = __ldg((const float4*)d_g + gw * 4 + q);  // once per node

    for (int i = beg + es; i < end; i += 8) {
        int2 a  = d_adj[i];                  // coalesced stream
        float w = __int_as_float(a.y);
        float* p = d_agg + a.x * HID + q * 4;
        asm volatile("red.global.add.v4.f32 [%0], {%1,%2,%3,%4};"
                     :: "l"(p), "f"(w * g.x), "f"(w * g.y),
                        "f"(w * g.z), "f"(w * g.w)
                     : "memory");
    }
}

// ---- 7. fused: h = relu(dinv*(agg+g)+b1);  g = dinv*(h @ W2); zero agg ------
__global__ void k_combine_gemm2(const float* __restrict__ b1,
                                const float* __restrict__ W2) {
    __shared__ float hs[16 * HID];
    __shared__ float W2s[HID * HID];
    int t = threadIdx.x;
    if (t < HID * HID) W2s[t] = W2[t];

    int nloc = t >> 4;
    int node = blockIdx.x * 16 + nloc;
    int c    = t & 15;
    bool ok  = (node < NN);
    float dv = 0.0f;
    int idx  = 0;
    if (ok) {
        idx = node * HID + c;
        dv  = d_dinv[node];
        float v = dv * (d_agg[idx] + d_g[idx]) + b1[c];
        hs[t] = fmaxf(v, 0.0f);
    }
    __syncthreads();
    if (!ok) return;

    float acc = 0.0f;
#pragma unroll
    for (int k = 0; k < HID; k++)
        acc += hs[nloc * HID + k] * W2s[k * HID + c];

    d_g[idx]   = dv * acc;
    d_agg[idx] = 0.0f;                      // zero for push pass 2
}

// ---- 8. final: out = relu(dinv*(agg+g)+b2) @ Wout + bout --------------------
__global__ void k_out(const float* __restrict__ b2,
                      const float* __restrict__ Wout,
                      const float* __restrict__ bout,
                      float* __restrict__ out) {
    int i = blockIdx.x * blockDim.x + threadIdx.x;
    if (i >= NN) return;
    float dv = d_dinv[i];
    const float4* a4 = (const float4*)d_agg + i * 4;
    const float4* g4 = (const float4*)d_g   + i * 4;
    float s = 0.0f;
#pragma unroll
    for (int q = 0; q < 4; q++) {
        float4 a = a4[q], g = g4[q];
        int c = q * 4;
        s += fmaxf(dv * (a.x + g.x) + __ldg(b2 + c + 0), 0.0f) * __ldg(Wout + c + 0);
        s += fmaxf(dv * (a.y + g.y) + __ldg(b2 + c + 1), 0.0f) * __ldg(Wout + c + 1);
        s += fmaxf(dv * (a.z + g.z) + __ldg(b2 + c + 2), 0.0f) * __ldg(Wout + c + 2);
        s += fmaxf(dv * (a.w + g.w) + __ldg(b2 + c + 3), 0.0f) * __ldg(Wout + c + 3);
    }
    out[i] = s + __ldg(bout);
}

extern "C" void kernel_launch(void* const* d_in, const int* in_sizes, int n_in,
                              void* d_out, int out_size) {
    const float* x    = (const float*)d_in[0];
    const int*   ei   = (const int*)d_in[1];   // [2, NE] int32
    const float* ea   = (const float*)d_in[2];
    const float* W1   = (const float*)d_in[5];
    const float* b1   = (const float*)d_in[6];
    const float* W2   = (const float*)d_in[7];
    const float* b2   = (const float*)d_in[8];
    const float* Wout = (const float*)d_in[9];
    const float* bout = (const float*)d_in[10];
    float*       out  = (float*)d_out;

    const int* row = ei;
    const int* col = ei + NE;

    const int T = 256;
    int gE  = (NE + T - 1) / T;            // edge-wise
    int gG  = (NN + 15) / 16;              // 16 nodes/block
    int gW  = (NN * 32 + T - 1) / T;       // warp-per-node
    int gN  = (NN + T - 1) / T;            // node-wise

    // CSC build + normalization (cnt/cur/deg are zero on entry; reset in-pipeline)
    k_count_deg<<<gE, T>>>(row, col, ea);
    k_scan1<<<NBLK, 256>>>();
    k_scan2<<<1, 512>>>();
    k_scan3<<<NBLK, 256>>>();              // also zeroes d_cnt
    k_fill<<<gE, T>>>(row, col, ea);
    k_dinv<<<gN, T>>>();                   // also zeroes d_deg, d_cur

    // layer 1
    k_gemm1<<<gG, T>>>(x, W1);             // also zeroes agg
    k_push<<<gW, T>>>();
    k_combine_gemm2<<<gG, T>>>(b1, W2);    // also zeroes agg

    // layer 2
    k_push<<<gW, T>>>();

    // fused combine + output projection
    k_out<<<gN, T>>>(b2, Wout, bout, out);
}

// round 8
// speedup vs baseline: 1.6657x; 1.6657x over previous
#include <cuda_runtime.h>
#include <math.h>

#define NN 100000
#define NE 3200000
#define HID 16
#define ES  (NE / 4)             // 800000 edge stripe

// Scratch (static device globals — zero-initialized at load)
__device__ float d_deg [NN];     // zero at load; re-zeroed by k_dinv each call
__device__ float d_dinv[NN];
__device__ float d_g  [NN * HID];
__device__ float d_agg[NN * HID];

// ---- degree accumulate (1 edge/thread) -------------------------------------
__global__ void k_deg_acc(const int* __restrict__ col,
                          const float* __restrict__ ew) {
    int e = blockIdx.x * blockDim.x + threadIdx.x;
    if (e < NE) atomicAdd(&d_deg[col[e]], ew[e]);
}

// dinv = rsqrt(1 + deg); reset deg for next replay
__global__ void k_dinv() {
    int i = blockIdx.x * blockDim.x + threadIdx.x;
    if (i < NN) {
        d_dinv[i] = rsqrtf(1.0f + d_deg[i]);
        d_deg[i] = 0.0f;
    }
}

// ---- layer-1 GEMM: g = dinv * (x @ W1); zero agg ---------------------------
// 256 threads = 16 nodes x 16 channels. WPAD=132 (≡4 mod 32): LDS.128 of Wt
// is conflict-free per 8-lane phase (banks 4(c+k) mod 32 cover all 32).
#define WPAD 132
__global__ void k_gemm1(const float* __restrict__ x,
                        const float* __restrict__ W1) {
    __shared__ float xs[16 * 128];
    __shared__ float Wt[HID * WPAD];
    int t = threadIdx.x;
    int base = blockIdx.x * 16;
    int nvalid = NN - base; if (nvalid > 16) nvalid = 16;

    const float4* xg = (const float4*)x + (size_t)base * 32;
    float4* xs4 = (float4*)xs;
    int n4 = nvalid * 32;
    for (int j = t; j < n4; j += 256) xs4[j] = xg[j];
    for (int j = t; j < 128 * HID; j += 256) {
        int k = j >> 4, c = j & 15;
        Wt[c * WPAD + k] = W1[j];
    }
    __syncthreads();

    int nloc = t >> 4;
    int node = base + nloc;
    int c    = t & 15;
    if (node >= NN) return;

    float acc = 0.0f;
    const float4* xrow = (const float4*)(xs + nloc * 128);
    const float*  wrow = Wt + c * WPAD;
#pragma unroll
    for (int kk = 0; kk < 32; kk++) {
        float4 xv = xrow[kk];                         // broadcast
        float4 wv = *(const float4*)(wrow + kk * 4);  // conflict-free LDS.128
        acc += xv.x * wv.x + xv.y * wv.y + xv.z * wv.z + xv.w * wv.w;
    }
    int idx = node * HID + c;
    d_g[idx]   = d_dinv[node] * acc;
    d_agg[idx] = 0.0f;                                // zero for edge pass 1
}

// ---- edge scatter: agg[col] += ew * g[row] ---------------------------------
// 4 threads per edge-slot, 4 striped edges per thread. All 4 gathers issued
// before any RED (MLP=4 hides L2 latency); REDs are fire-and-forget.
__global__ void k_edges(const int* __restrict__ row,
                        const int* __restrict__ col,
                        const float* __restrict__ ew) {
    int idx = blockIdx.x * 256 + threadIdx.x;
    int e0 = idx >> 2;          // 0 .. ES-1
    int q  = idx & 3;
    if (e0 >= ES) return;

    int    r[4], d[4];
    float  w[4];
    float4 g[4];
#pragma unroll
    for (int j = 0; j < 4; j++) {
        int e = e0 + j * ES;
        r[j] = __ldg(row + e);
        d[j] = __ldg(col + e);
        w[j] = __ldg(ew  + e);
    }
#pragma unroll
    for (int j = 0; j < 4; j++)
        g[j] = __ldg((const float4*)d_g + r[j] * 4 + q);
#pragma unroll
    for (int j = 0; j < 4; j++) {
        float* p = d_agg + d[j] * HID + q * 4;
        asm volatile("red.global.add.v4.f32 [%0], {%1,%2,%3,%4};"
                     :: "l"(p), "f"(w[j] * g[j].x), "f"(w[j] * g[j].y),
                        "f"(w[j] * g[j].z), "f"(w[j] * g[j].w)
                     : "memory");
    }
}

// ---- fused: h = relu(dinv*(agg+g)+b1);  g = dinv*(h @ W2); zero agg --------
__global__ void k_combine_gemm2(const float* __restrict__ b1,
                                const float* __restrict__ W2) {
    __shared__ float hs[16 * HID];
    __shared__ float W2s[HID * HID];
    int t = threadIdx.x;
    if (t < HID * HID) W2s[t] = W2[t];

    int nloc = t >> 4;
    int node = blockIdx.x * 16 + nloc;
    int c    = t & 15;
    bool ok  = (node < NN);
    float dv = 0.0f;
    int idx  = 0;
    if (ok) {
        idx = node * HID + c;
        dv  = d_dinv[node];
        float v = dv * (d_agg[idx] + d_g[idx]) + b1[c];
        hs[t] = fmaxf(v, 0.0f);
    }
    __syncthreads();
    if (!ok) return;

    float acc = 0.0f;
#pragma unroll
    for (int k = 0; k < HID; k++)
        acc += hs[nloc * HID + k] * W2s[k * HID + c];

    d_g[idx]   = dv * acc;
    d_agg[idx] = 0.0f;                                // zero for edge pass 2
}

// ---- final: out = relu(dinv*(agg+g)+b2) @ Wout + bout ----------------------
__global__ void k_out(const float* __restrict__ b2,
                      const float* __restrict__ Wout,
                      const float* __restrict__ bout,
                      float* __restrict__ out) {
    int i = blockIdx.x * blockDim.x + threadIdx.x;
    if (i >= NN) return;
    float dv = d_dinv[i];
    const float4* a4 = (const float4*)d_agg + i * 4;
    const float4* g4 = (const float4*)d_g   + i * 4;
    float s = 0.0f;
#pragma unroll
    for (int q = 0; q < 4; q++) {
        float4 a = a4[q], g = g4[q];
        int c = q * 4;
        s += fmaxf(dv * (a.x + g.x) + __ldg(b2 + c + 0), 0.0f) * __ldg(Wout + c + 0);
        s += fmaxf(dv * (a.y + g.y) + __ldg(b2 + c + 1), 0.0f) * __ldg(Wout + c + 1);
        s += fmaxf(dv * (a.z + g.z) + __ldg(b2 + c + 2), 0.0f) * __ldg(Wout + c + 2);
        s += fmaxf(dv * (a.w + g.w) + __ldg(b2 + c + 3), 0.0f) * __ldg(Wout + c + 3);
    }
    out[i] = s + __ldg(bout);
}

extern "C" void kernel_launch(void* const* d_in, const int* in_sizes, int n_in,
                              void* d_out, int out_size) {
    const float* x    = (const float*)d_in[0];
    const int*   ei   = (const int*)d_in[1];   // [2, NE] int32
    const float* ea   = (const float*)d_in[2];
    const float* W1   = (const float*)d_in[5];
    const float* b1   = (const float*)d_in[6];
    const float* W2   = (const float*)d_in[7];
    const float* b2   = (const float*)d_in[8];
    const float* Wout = (const float*)d_in[9];
    const float* bout = (const float*)d_in[10];
    float*       out  = (float*)d_out;

    const int* row = ei;
    const int* col = ei + NE;

    const int T = 256;
    int gN  = (NN + T - 1) / T;
    int gE  = (NE + T - 1) / T;
    int gG  = (NN + 15) / 16;
    int gE4 = (ES * 4 + T - 1) / T;        // 4 threads/slot, 4 edges/thread

    // normalization (d_deg zero on entry; k_dinv re-zeroes it)
    k_deg_acc<<<gE, T>>>(col, ea);
    k_dinv<<<gN, T>>>();

    // layer 1
    k_gemm1<<<gG, T>>>(x, W1);             // also zeroes agg
    k_edges<<<gE4, T>>>(row, col, ea);
    k_combine_gemm2<<<gG, T>>>(b1, W2);    // also zeroes agg

    // layer 2
    k_edges<<<gE4, T>>>(row, col, ea);

    // fused combine + output projection
    k_out<<<gN, T>>>(b2, Wout, bout, out);
}

// round 9
// speedup vs baseline: 1.6696x; 1.0024x over previous
#include <cuda_runtime.h>
#include <math.h>

#define NN 100000
#define NE 3200000
#define HID 16
#define ES  (NE / 4)             // 800000 edge stripe
#define GG  ((NN + 15) / 16)     // gemm blocks (6250)
#define GE  ((NE + 255) / 256)   // deg blocks (12500)

// Scratch (static device globals — zero-initialized at load)
__device__ float d_deg [NN];     // zero at load; re-zeroed by k_dinv_scale
__device__ float d_dinv[NN];
__device__ float d_g  [NN * HID];
__device__ float d_agg[NN * HID];

// ---- fused: [blocks 0..GG) u = x@W1 (unscaled) + zero agg;
//             [blocks GG..GG+GE) weighted in-degree atomics ------------------
#define WPAD 132
__global__ void k_gemm1_deg(const float* __restrict__ x,
                            const float* __restrict__ W1,
                            const int* __restrict__ col,
                            const float* __restrict__ ew) {
    if (blockIdx.x >= GG) {
        // degree phase: 1 edge/thread
        int e = (blockIdx.x - GG) * 256 + threadIdx.x;
        if (e < NE) atomicAdd(&d_deg[col[e]], ew[e]);
        return;
    }
    // gemm phase: 16 nodes x 16 channels
    __shared__ float xs[16 * 128];
    __shared__ float Wt[HID * WPAD];   // WPAD=132 (≡4 mod 32): conflict-free LDS.128
    int t = threadIdx.x;
    int base = blockIdx.x * 16;
    int nvalid = NN - base; if (nvalid > 16) nvalid = 16;

    const float4* xg = (const float4*)x + (size_t)base * 32;
    float4* xs4 = (float4*)xs;
    int n4 = nvalid * 32;
    for (int j = t; j < n4; j += 256) xs4[j] = xg[j];
    for (int j = t; j < 128 * HID; j += 256) {
        int k = j >> 4, c = j & 15;
        Wt[c * WPAD + k] = W1[j];
    }
    __syncthreads();

    int nloc = t >> 4;
    int node = base + nloc;
    int c    = t & 15;
    if (node >= NN) return;

    float acc = 0.0f;
    const float4* xrow = (const float4*)(xs + nloc * 128);
    const float*  wrow = Wt + c * WPAD;
#pragma unroll
    for (int kk = 0; kk < 32; kk++) {
        float4 xv = xrow[kk];                         // broadcast
        float4 wv = *(const float4*)(wrow + kk * 4);  // conflict-free LDS.128
        acc += xv.x * wv.x + xv.y * wv.y + xv.z * wv.z + xv.w * wv.w;
    }
    int idx = node * HID + c;
    d_g[idx]   = acc;                                 // unscaled
    d_agg[idx] = 0.0f;                                // zero for edge pass 1
}

// ---- dinv = rsqrt(1+deg); g *= dinv; reset deg ------------------------------
__global__ void k_dinv_scale() {
    int idx = blockIdx.x * blockDim.x + threadIdx.x;
    if (idx >= NN * HID) return;
    int node = idx >> 4;
    float dv = rsqrtf(1.0f + d_deg[node]);   // broadcast load, cheap MUFU
    d_g[idx] *= dv;
    if ((idx & 15) == 0) {
        d_dinv[node] = dv;
        d_deg[node]  = 0.0f;                 // reset for next replay
    }
}

// ---- edge scatter: agg[col] += ew * g[row] ---------------------------------
// 4 threads per edge-slot, 4 striped edges per thread (MLP=4 gathers).
__global__ void k_edges(const int* __restrict__ row,
                        const int* __restrict__ col,
                        const float* __restrict__ ew) {
    int idx = blockIdx.x * 256 + threadIdx.x;
    int e0 = idx >> 2;          // 0 .. ES-1
    int q  = idx & 3;
    if (e0 >= ES) return;

    int    r[4], d[4];
    float  w[4];
    float4 g[4];
#pragma unroll
    for (int j = 0; j < 4; j++) {
        int e = e0 + j * ES;
        r[j] = __ldg(row + e);
        d[j] = __ldg(col + e);
        w[j] = __ldg(ew  + e);
    }
#pragma unroll
    for (int j = 0; j < 4; j++)
        g[j] = __ldg((const float4*)d_g + r[j] * 4 + q);
#pragma unroll
    for (int j = 0; j < 4; j++) {
        float* p = d_agg + d[j] * HID + q * 4;
        asm volatile("red.global.add.v4.f32 [%0], {%1,%2,%3,%4};"
                     :: "l"(p), "f"(w[j] * g[j].x), "f"(w[j] * g[j].y),
                        "f"(w[j] * g[j].z), "f"(w[j] * g[j].w)
                     : "memory");
    }
}

// ---- fused: h = relu(dinv*(agg+g)+b1);  g = dinv*(h @ W2); zero agg --------
__global__ void k_combine_gemm2(const float* __restrict__ b1,
                                const float* __restrict__ W2) {
    __shared__ float hs[16 * HID];
    __shared__ float W2s[HID * HID];
    int t = threadIdx.x;
    if (t < HID * HID) W2s[t] = W2[t];

    int nloc = t >> 4;
    int node = blockIdx.x * 16 + nloc;
    int c    = t & 15;
    bool ok  = (node < NN);
    float dv = 0.0f;
    int idx  = 0;
    if (ok) {
        idx = node * HID + c;
        dv  = d_dinv[node];
        float v = dv * (d_agg[idx] + d_g[idx]) + b1[c];
        hs[t] = fmaxf(v, 0.0f);
    }
    __syncthreads();
    if (!ok) return;

    float acc = 0.0f;
#pragma unroll
    for (int k = 0; k < HID; k++)
        acc += hs[nloc * HID + k] * W2s[k * HID + c];

    d_g[idx]   = dv * acc;
    d_agg[idx] = 0.0f;                                // zero for edge pass 2
}

// ---- final: out = relu(dinv*(agg+g)+b2) @ Wout + bout ----------------------
__global__ void k_out(const float* __restrict__ b2,
                      const float* __restrict__ Wout,
                      const float* __restrict__ bout,
                      float* __restrict__ out) {
    int i = blockIdx.x * blockDim.x + threadIdx.x;
    if (i >= NN) return;
    float dv = d_dinv[i];
    const float4* a4 = (const float4*)d_agg + i * 4;
    const float4* g4 = (const float4*)d_g   + i * 4;
    float s = 0.0f;
#pragma unroll
    for (int q = 0; q < 4; q++) {
        float4 a = a4[q], g = g4[q];
        int c = q * 4;
        s += fmaxf(dv * (a.x + g.x) + __ldg(b2 + c + 0), 0.0f) * __ldg(Wout + c + 0);
        s += fmaxf(dv * (a.y + g.y) + __ldg(b2 + c + 1), 0.0f) * __ldg(Wout + c + 1);
        s += fmaxf(dv * (a.z + g.z) + __ldg(b2 + c + 2), 0.0f) * __ldg(Wout + c + 2);
        s += fmaxf(dv * (a.w + g.w) + __ldg(b2 + c + 3), 0.0f) * __ldg(Wout + c + 3);
    }
    out[i] = s + __ldg(bout);
}

extern "C" void kernel_launch(void* const* d_in, const int* in_sizes, int n_in,
                              void* d_out, int out_size) {
    const float* x    = (const float*)d_in[0];
    const int*   ei   = (const int*)d_in[1];   // [2, NE] int32
    const float* ea   = (const float*)d_in[2];
    const float* W1   = (const float*)d_in[5];
    const float* b1   = (const float*)d_in[6];
    const float* W2   = (const float*)d_in[7];
    const float* b2   = (const float*)d_in[8];
    const float* Wout = (const float*)d_in[9];
    const float* bout = (const float*)d_in[10];
    float*       out  = (float*)d_out;

    const int* row = ei;
    const int* col = ei + NE;

    const int T = 256;
    int gN   = (NN + T - 1) / T;
    int gNC  = (NN * HID + T - 1) / T;
    int gE4  = (ES * 4 + T - 1) / T;       // 4 threads/slot, 4 edges/thread

    // fused: gemm1 (unscaled) + degree atomics, co-scheduled
    k_gemm1_deg<<<GG + GE, T>>>(x, W1, col, ea);
    k_dinv_scale<<<gNC, T>>>();            // dinv, scale g, reset deg

    // layer 1
    k_edges<<<gE4, T>>>(row, col, ea);
    k_combine_gemm2<<<GG, T>>>(b1, W2);    // also zeroes agg

    // layer 2
    k_edges<<<gE4, T>>>(row, col, ea);

    // fused combine + output projection
    k_out<<<gN, T>>>(b2, Wout, bout, out);
}